// round 15
// baseline (speedup 1.0000x reference)
#include <cuda_runtime.h>

#define N 192
#define TX 32
#define TY 8
#define NT 256
#define ZCHUNK 96
#define NCHUNK 2
#define PW 36             // TX + 4
#define PH 12             // TY + 4
#define PLANE (PH*PW)     // 432 words = 216 float2
#define HPAIRS 216
#define CXROWS 11
#define VOL ((size_t)N*(size_t)N*(size_t)N)

__device__ __forceinline__ float ex2f(float x) {
    float r;
    asm("ex2.approx.f32 %0, %1;" : "=f"(r) : "f"(x));
    return r;
}

__global__ void __launch_bounds__(NT, 4)
mind_kernel(const float* __restrict__ img, float* __restrict__ out) {
    __shared__ float  s_img[6][PLANE];              // plane ring, slot = plane % 6
    __shared__ float4 s_cx[6][CXROWS][TX];          // 3 pairs of exchange buffers

    const int lx  = threadIdx.x;
    const int ly  = threadIdx.y;
    const int tid = ly * TX + lx;
    const int bx0 = blockIdx.x * TX;
    const int by0 = blockIdx.y * TY;
    const int b   = blockIdx.z >> 1;                 // NCHUNK == 2
    const int z0  = (blockIdx.z & 1) * ZCHUNK;

    constexpr float A   = 0.018315639f;              // exp(-4): 1D Gaussian side tap
    constexpr float C6  = 6.683808e-08f;             // 6*EPS*(1+2A)^3  (NORM folded)
    constexpr float L6  = 8.65617025f;               // 6*log2(e): exp->ex2 folded
    constexpr float EPS = 1e-8f;

    const float* imgb = img + (size_t)b * VOL;
    float* outb = out + (size_t)b * 6 * VOL;

    // ---- hoisted halo-load geometry: one float2 pair per thread (tid < 216) ----
    const bool hasL = (tid < HPAIRS);
    int hp_off = 0, hp_ok = 0;
    {
        const int w0 = 2 * tid;                      // first word of the pair
        const int px = w0 % PW, py = w0 / PW;        // px even; pair stays in row
        const int gxh = bx0 + px - 2, gyh = by0 + py - 2;
        // pair-shared validity: gxh even => gxh,gxh+1 jointly in [0,191] iff gxh in [0,190]
        hp_ok  = (gxh >= 0) & (gxh <= N - 2) & ((unsigned)gyh < (unsigned)N);
        hp_off = gyh * N + gxh;
    }
    auto prefetch = [&](int zp, float2& v) {
        v = make_float2(0.f, 0.f);
        if (hasL) {
            const int zok = (unsigned)zp < (unsigned)N;
            if (zok & hp_ok)
                v = *reinterpret_cast<const float2*>(imgb + (size_t)zp * (N * N) + hp_off);
        }
    };
    auto commit = [&](float* dst, float2 v) {
        if (hasL)
            reinterpret_cast<float2*>(dst)[tid] = v;
    };

    // ---- hoisted per-thread geometry ----
    const int   gx   = bx0 + lx;
    const int   gy   = by0 + ly;
    const float wl   = (gx >= 1)     ? A : 0.f;   // x-conv border masks
    const float wr   = (gx <= N - 2) ? A : 0.f;
    const float wAy  = (gy == N - 1) ? 0.f : A;   // -y: drop far-edge tap
    const float wAy0 = (gy == 0)     ? 0.f : A;   // +y: mask contaminated y=0 halo row

    const int  rbA  = ly * PW + lx;               // posA: tile row ly-2
    const int  idxA = ly;
    const int  rbB  = (TY + ly) * PW + lx;        // posB: tile row TY-2+ly (ly<3)
    const int  idxB = TY + ly;
    const bool hasB = (ly < 3);

    // stage2 for TWO consecutive planes at one row position (shares PB center row)
    auto stage2_pair = [&](const float* PA, const float* PB, const float* PC,
                           float4* cxA, float4* cxB, int rb, int idx) {
        const float a0 = PA[rb],     a1 = PA[rb + 1], a2 = PA[rb + 2];
        const float a3 = PA[rb + 3], a4 = PA[rb + 4];
        const float u0 = PA[rb + PW + 1], u1 = PA[rb + PW + 2], u2 = PA[rb + PW + 3];
        const float p0 = PB[rb + 1], p1 = PB[rb + 2], p2 = PB[rb + 3];
        {
            const float q0 = a1 - a0, q1 = a2 - a1, q2 = a3 - a2, q3 = a4 - a3;
            const float s0 = q0 * q0, s1 = q1 * q1, s2 = q2 * q2, s3 = q3 * q3;
            const float cxp = fmaf(wr, s3, fmaf(wl, s1, s2));
            const float cxm = fmaf(wr, s2, fmaf(wl, s0, s1));
            const float d0 = u0 - a1, d1 = u1 - a2, d2 = u2 - a3;
            const float cyp = fmaf(wr, d2 * d2, fmaf(wl, d0 * d0, d1 * d1));
            const float e0 = p0 - a1, e1 = p1 - a2, e2 = p2 - a3;
            const float czp = fmaf(wr, e2 * e2, fmaf(wl, e0 * e0, e1 * e1));
            cxA[idx * TX + lx] = make_float4(czp, cyp, cxp, cxm);
        }
        const float b0 = PB[rb], b4 = PB[rb + 4];
        const float v0 = PB[rb + PW + 1], v1 = PB[rb + PW + 2], v2 = PB[rb + PW + 3];
        const float w0 = PC[rb + 1], w1 = PC[rb + 2], w2 = PC[rb + 3];
        {
            const float q0 = p0 - b0, q1 = p1 - p0, q2 = p2 - p1, q3 = b4 - p2;
            const float s0 = q0 * q0, s1 = q1 * q1, s2 = q2 * q2, s3 = q3 * q3;
            const float cxp = fmaf(wr, s3, fmaf(wl, s1, s2));
            const float cxm = fmaf(wr, s2, fmaf(wl, s0, s1));
            const float d0 = v0 - p0, d1 = v1 - p1, d2 = v2 - p2;
            const float cyp = fmaf(wr, d2 * d2, fmaf(wl, d0 * d0, d1 * d1));
            const float e0 = w0 - p0, e1 = w1 - p1, e2 = w2 - p2;
            const float czp = fmaf(wr, e2 * e2, fmaf(wl, e0 * e0, e1 * e1));
            cxB[idx * TX + lx] = make_float4(czp, cyp, cxp, cxm);
        }
    };

    // register rings of xy-convolved fields
    float Tza = 0.f, Tzb = 0.f, Tzc = 0.f, Tzd = 0.f;
    float Typa = 0.f, Typb = 0.f, Typc = 0.f;
    float Tyma = 0.f, Tymb = 0.f, Tymc = 0.f;
    float Txpa = 0.f, Txpb = 0.f, Txpc = 0.f;
    float Txma = 0.f, Txmb = 0.f, Txmc = 0.f;

    // per-plane stage3: shift rings, fold in one cx buffer, optionally emit zo
    auto stage3 = [&](const float4* cxr, bool doOut, int zo) {
        // row ly contributes only its cy field (-y delayed tap): scalar load
        const float r0y = reinterpret_cast<const float*>(cxr + ly * TX + lx)[1];
        const float4 r1 = cxr[(ly + 1) * TX + lx];
        const float4 r2 = cxr[(ly + 2) * TX + lx];
        const float4 r3 = cxr[(ly + 3) * TX + lx];
        Tza = Tzb; Tzb = Tzc; Tzc = Tzd;
        Typa = Typb; Typb = Typc;
        Tyma = Tymb; Tymb = Tymc;
        Txpa = Txpb; Txpb = Txpc;
        Txma = Txmb; Txmb = Txmc;
        Tzd  = fmaf(A, r1.x + r3.x, r2.x);
        Typc = fmaf(wAy0, r1.y, fmaf(A, r3.y, r2.y));
        Tymc = fmaf(wAy, r2.y, fmaf(A, r0y, r1.y));
        Txpc = fmaf(A, r1.z + r3.z, r2.z);
        Txmc = fmaf(A, r1.w + r3.w, r2.w);
        if (doOut) {
            const float wAz  = (zo == N - 1) ? 0.f : A;
            const float wAz0 = (zo == 0)     ? 0.f : A;
            float Dp[6];
            Dp[0] = fmaf(wAz0, Tzb, fmaf(A, Tzd, Tzc));
            Dp[1] = fmaf(wAz, Tzc, fmaf(A, Tza, Tzb));
            Dp[2] = fmaf(A, Typa + Typc, Typb);
            Dp[3] = fmaf(A, Tyma + Tymc, Tymb);
            Dp[4] = fmaf(A, Txpa + Txpc, Txpb);
            Dp[5] = fmaf(A, Txma + Txmc, Txmb);
            float sd = 0.f;
#pragma unroll
            for (int c = 0; c < 6; c++) sd += Dp[c];
            // invL = 6*log2e / (sd*NORM6 + eps-term): exp->ex2 conversion folded in
            const float invL = __fdividef(L6, sd + C6);
            float num[6];
            float s = 0.f;
#pragma unroll
            for (int c = 0; c < 6; c++) { num[c] = ex2f(-Dp[c] * invL); s += num[c]; }
            const float invs = __fdividef(1.f, s + EPS);
            const size_t base = ((size_t)zo * N + gy) * N + gx;
#pragma unroll
            for (int c = 0; c < 6; c++)
                __stcs(&outb[(size_t)c * VOL + base], num[c] * invs);  // evict-first
        }
    };

    // preload planes 0,1,2 (z = z0-2..z0) into slots 0,1,2; prefetch planes 3,4
    {
        float2 v;
        prefetch(z0 - 2, v); commit(s_img[0], v);
        prefetch(z0 - 1, v); commit(s_img[1], v);
        prefetch(z0,     v); commit(s_img[2], v);
    }
    float2 pa, pb;
    prefetch(z0 + 1, pa);
    prefetch(z0 + 2, pb);
    __syncthreads();

#pragma unroll 3
    for (int t = 0; t <= 50; ++t) {
        // commit planes 2t+3, 2t+4 (slots disjoint from this iter's reads mod 6)
        commit(s_img[(2 * t + 3) % 6], pa);
        commit(s_img[(2 * t + 4) % 6], pb);
        prefetch(z0 + 3 + 2 * t, pa);                // plane 2t+5
        prefetch(z0 + 4 + 2 * t, pb);                // plane 2t+6

        // stage2 for planes 2t (A: z=z0-2+2t) and 2t+1 (B)
        const float* PA = s_img[(2 * t) % 6];
        const float* PB = s_img[(2 * t + 1) % 6];
        const float* PC = s_img[(2 * t + 2) % 6];
        float4* cxA = &s_cx[(t % 3) * 2][0][0];
        float4* cxB = &s_cx[(t % 3) * 2 + 1][0][0];
        stage2_pair(PA, PB, PC, cxA, cxB, rbA, idxA);
        if (hasB) stage2_pair(PA, PB, PC, cxA, cxB, rbB, idxB);

        __syncthreads();                             // one barrier per 2 planes

        if (t >= 1) {
            // stage3 over the pair written at t-1: planes 2t-2, 2t-1
            const float4* crA = &s_cx[((t + 2) % 3) * 2][0][0];
            const float4* crB = crA + CXROWS * TX;
            stage3(crA, t >= 3,            z0 - 5 + 2 * t);   // zo plane 2t-3
            stage3(crB, t >= 2 && t <= 49, z0 - 4 + 2 * t);   // zo plane 2t-2
        }
    }
}

extern "C" void kernel_launch(void* const* d_in, const int* in_sizes, int n_in,
                              void* d_out, int out_size) {
    const float* img = (const float*)d_in[0];
    float* out = (float*)d_out;
    const int B = in_sizes[0] / (int)(N * N * N);
    dim3 block(TX, TY, 1);
    dim3 grid(N / TX, N / TY, B * NCHUNK);
    mind_kernel<<<grid, block>>>(img, out);
}

// round 16
// speedup vs baseline: 1.0288x; 1.0288x over previous
#include <cuda_runtime.h>

#define N 192
#define TX 32
#define TY 8
#define NT 256
#define ZCHUNK 96
#define NCHUNK 2
#define PW 36             // TX + 4
#define PH 12             // TY + 4
#define PLANE (PH*PW)     // 432
#define CXROWS 11
#define VOL ((size_t)N*(size_t)N*(size_t)N)

__device__ __forceinline__ float ex2f(float x) {
    float r;
    asm("ex2.approx.f32 %0, %1;" : "=f"(r) : "f"(x));
    return r;
}

__global__ void __launch_bounds__(NT, 4)
mind_kernel(const float* __restrict__ img, float* __restrict__ out) {
    __shared__ float  s_img[6][PLANE];              // plane ring, slot = plane % 6
    __shared__ float4 s_cx[6][CXROWS][TX];          // 3 pairs of exchange buffers

    const int lx  = threadIdx.x;
    const int ly  = threadIdx.y;
    const int tid = ly * TX + lx;
    const int bx0 = blockIdx.x * TX;
    const int by0 = blockIdx.y * TY;
    const int b   = blockIdx.z >> 1;                 // NCHUNK == 2
    const int z0  = (blockIdx.z & 1) * ZCHUNK;

    constexpr float A   = 0.018315639f;              // exp(-4): 1D Gaussian side tap
    constexpr float C6  = 6.683808e-08f;             // 6*EPS*(1+2A)^3  (NORM folded)
    constexpr float L6  = 8.65617025f;               // 6*log2(e): exp->ex2 folded
    constexpr float EPS = 1e-8f;

    const float* imgb = img + (size_t)b * VOL;
    float* outb = out + (size_t)b * 6 * VOL;

    // ---- hoisted halo-load geometry (balanced: all 256 threads) ----
    int h1_off, h1_ok;
    {
        const int px = tid % PW, py = tid / PW;
        const int gxh = bx0 + px - 2, gyh = by0 + py - 2;
        h1_ok  = ((unsigned)gxh < (unsigned)N) & ((unsigned)gyh < (unsigned)N);
        h1_off = gyh * N + gxh;
    }
    int h2_off = 0, h2_ok = 0;
    const bool has2 = (tid < PLANE - NT);
    {
        const int i = tid + NT;
        if (i < PLANE) {
            const int px = i % PW, py = i / PW;
            const int gxh = bx0 + px - 2, gyh = by0 + py - 2;
            h2_ok  = ((unsigned)gxh < (unsigned)N) & ((unsigned)gyh < (unsigned)N);
            h2_off = gyh * N + gxh;
        }
    }
    auto prefetch = [&](int zp, float& v1, float& v2) {
        const int zok = (unsigned)zp < (unsigned)N;
        const float* src = imgb + (size_t)zp * (N * N);
        v1 = 0.f; v2 = 0.f;
        if (zok & h1_ok) v1 = __ldg(src + h1_off);
        if (has2 && (zok & h2_ok)) v2 = __ldg(src + h2_off);
    };
    auto commit = [&](float* dst, float v1, float v2) {
        dst[tid] = v1;
        if (has2) dst[tid + NT] = v2;
    };

    // ---- hoisted per-thread geometry ----
    const int   gx   = bx0 + lx;
    const int   gy   = by0 + ly;
    const float wl   = (gx >= 1)     ? A : 0.f;   // x-conv border masks
    const float wr   = (gx <= N - 2) ? A : 0.f;
    const float wAy  = (gy == N - 1) ? 0.f : A;   // -y: drop far-edge tap
    const float wAy0 = (gy == 0)     ? 0.f : A;   // +y: mask contaminated y=0 halo row

    const int  rbA  = ly * PW + lx;               // posA: tile row ly-2
    const int  idxA = ly;
    const int  rbB  = (TY + ly) * PW + lx;        // posB: tile row TY-2+ly (ly<3)
    const int  idxB = TY + ly;
    const bool hasB = (ly < 3);

    // stage2 for TWO consecutive planes at one row position (shares PB center row)
    auto stage2_pair = [&](const float* PA, const float* PB, const float* PC,
                           float4* cxA, float4* cxB, int rb, int idx) {
        const float a0 = PA[rb],     a1 = PA[rb + 1], a2 = PA[rb + 2];
        const float a3 = PA[rb + 3], a4 = PA[rb + 4];
        const float u0 = PA[rb + PW + 1], u1 = PA[rb + PW + 2], u2 = PA[rb + PW + 3];
        const float p0 = PB[rb + 1], p1 = PB[rb + 2], p2 = PB[rb + 3];
        {
            const float q0 = a1 - a0, q1 = a2 - a1, q2 = a3 - a2, q3 = a4 - a3;
            const float s0 = q0 * q0, s1 = q1 * q1, s2 = q2 * q2, s3 = q3 * q3;
            const float cxp = fmaf(wr, s3, fmaf(wl, s1, s2));
            const float cxm = fmaf(wr, s2, fmaf(wl, s0, s1));
            const float d0 = u0 - a1, d1 = u1 - a2, d2 = u2 - a3;
            const float cyp = fmaf(wr, d2 * d2, fmaf(wl, d0 * d0, d1 * d1));
            const float e0 = p0 - a1, e1 = p1 - a2, e2 = p2 - a3;
            const float czp = fmaf(wr, e2 * e2, fmaf(wl, e0 * e0, e1 * e1));
            cxA[idx * TX + lx] = make_float4(czp, cyp, cxp, cxm);
        }
        const float b0 = PB[rb], b4 = PB[rb + 4];
        const float v0 = PB[rb + PW + 1], v1 = PB[rb + PW + 2], v2 = PB[rb + PW + 3];
        const float w0 = PC[rb + 1], w1 = PC[rb + 2], w2 = PC[rb + 3];
        {
            const float q0 = p0 - b0, q1 = p1 - p0, q2 = p2 - p1, q3 = b4 - p2;
            const float s0 = q0 * q0, s1 = q1 * q1, s2 = q2 * q2, s3 = q3 * q3;
            const float cxp = fmaf(wr, s3, fmaf(wl, s1, s2));
            const float cxm = fmaf(wr, s2, fmaf(wl, s0, s1));
            const float d0 = v0 - p0, d1 = v1 - p1, d2 = v2 - p2;
            const float cyp = fmaf(wr, d2 * d2, fmaf(wl, d0 * d0, d1 * d1));
            const float e0 = w0 - p0, e1 = w1 - p1, e2 = w2 - p2;
            const float czp = fmaf(wr, e2 * e2, fmaf(wl, e0 * e0, e1 * e1));
            cxB[idx * TX + lx] = make_float4(czp, cyp, cxp, cxm);
        }
    };

    // register rings of xy-convolved fields
    float Tza = 0.f, Tzb = 0.f, Tzc = 0.f, Tzd = 0.f;
    float Typa = 0.f, Typb = 0.f, Typc = 0.f;
    float Tyma = 0.f, Tymb = 0.f, Tymc = 0.f;
    float Txpa = 0.f, Txpb = 0.f, Txpc = 0.f;
    float Txma = 0.f, Txmb = 0.f, Txmc = 0.f;

    // per-plane stage3: shift rings, fold in one cx buffer, optionally emit zo
    auto stage3 = [&](const float4* cxr, bool doOut, int zo) {
        // row ly contributes only its cy field (-y delayed tap): scalar load
        const float r0y = reinterpret_cast<const float*>(cxr + ly * TX + lx)[1];
        const float4 r1 = cxr[(ly + 1) * TX + lx];
        const float4 r2 = cxr[(ly + 2) * TX + lx];
        const float4 r3 = cxr[(ly + 3) * TX + lx];
        Tza = Tzb; Tzb = Tzc; Tzc = Tzd;
        Typa = Typb; Typb = Typc;
        Tyma = Tymb; Tymb = Tymc;
        Txpa = Txpb; Txpb = Txpc;
        Txma = Txmb; Txmb = Txmc;
        Tzd  = fmaf(A, r1.x + r3.x, r2.x);
        Typc = fmaf(wAy0, r1.y, fmaf(A, r3.y, r2.y));
        Tymc = fmaf(wAy, r2.y, fmaf(A, r0y, r1.y));
        Txpc = fmaf(A, r1.z + r3.z, r2.z);
        Txmc = fmaf(A, r1.w + r3.w, r2.w);
        if (doOut) {
            const float wAz  = (zo == N - 1) ? 0.f : A;
            const float wAz0 = (zo == 0)     ? 0.f : A;
            float Dp[6];
            Dp[0] = fmaf(wAz0, Tzb, fmaf(A, Tzd, Tzc));
            Dp[1] = fmaf(wAz, Tzc, fmaf(A, Tza, Tzb));
            Dp[2] = fmaf(A, Typa + Typc, Typb);
            Dp[3] = fmaf(A, Tyma + Tymc, Tymb);
            Dp[4] = fmaf(A, Txpa + Txpc, Txpb);
            Dp[5] = fmaf(A, Txma + Txmc, Txmb);
            float sd = 0.f;
#pragma unroll
            for (int c = 0; c < 6; c++) sd += Dp[c];
            // invL = 6*log2(e) / (sd + C6): exp->ex2 conversion folded into divide
            const float invL = __fdividef(L6, sd + C6);
            float num[6];
            float s = 0.f;
#pragma unroll
            for (int c = 0; c < 6; c++) { num[c] = ex2f(-Dp[c] * invL); s += num[c]; }
            const float invs = __fdividef(1.f, s + EPS);
            const size_t base = ((size_t)zo * N + gy) * N + gx;
#pragma unroll
            for (int c = 0; c < 6; c++)
                __stcs(&outb[(size_t)c * VOL + base], num[c] * invs);  // evict-first
        }
    };

    // preload planes 0,1,2 (z = z0-2..z0) into slots 0,1,2; prefetch planes 3,4
    {
        float a1v, a2v;
        prefetch(z0 - 2, a1v, a2v); commit(s_img[0], a1v, a2v);
        prefetch(z0 - 1, a1v, a2v); commit(s_img[1], a1v, a2v);
        prefetch(z0,     a1v, a2v); commit(s_img[2], a1v, a2v);
    }
    float pa1, pa2, pb1, pb2;
    prefetch(z0 + 1, pa1, pa2);
    prefetch(z0 + 2, pb1, pb2);
    __syncthreads();

#pragma unroll 3
    for (int t = 0; t <= 50; ++t) {
        // commit planes 2t+3, 2t+4 (slots disjoint from this iter's reads mod 6)
        commit(s_img[(2 * t + 3) % 6], pa1, pa2);
        commit(s_img[(2 * t + 4) % 6], pb1, pb2);
        prefetch(z0 + 3 + 2 * t, pa1, pa2);          // plane 2t+5
        prefetch(z0 + 4 + 2 * t, pb1, pb2);          // plane 2t+6

        // stage2 for planes 2t (A: z=z0-2+2t) and 2t+1 (B)
        const float* PA = s_img[(2 * t) % 6];
        const float* PB = s_img[(2 * t + 1) % 6];
        const float* PC = s_img[(2 * t + 2) % 6];
        float4* cxA = &s_cx[(t % 3) * 2][0][0];
        float4* cxB = &s_cx[(t % 3) * 2 + 1][0][0];
        stage2_pair(PA, PB, PC, cxA, cxB, rbA, idxA);
        if (hasB) stage2_pair(PA, PB, PC, cxA, cxB, rbB, idxB);

        __syncthreads();                             // one barrier per 2 planes

        if (t >= 1) {
            // stage3 over the pair written at t-1: planes 2t-2, 2t-1
            const float4* crA = &s_cx[((t + 2) % 3) * 2][0][0];
            const float4* crB = crA + CXROWS * TX;
            stage3(crA, t >= 3,            z0 - 5 + 2 * t);   // zo plane 2t-3
            stage3(crB, t >= 2 && t <= 49, z0 - 4 + 2 * t);   // zo plane 2t-2
        }
    }
}

extern "C" void kernel_launch(void* const* d_in, const int* in_sizes, int n_in,
                              void* d_out, int out_size) {
    const float* img = (const float*)d_in[0];
    float* out = (float*)d_out;
    const int B = in_sizes[0] / (int)(N * N * N);
    dim3 block(TX, TY, 1);
    dim3 grid(N / TX, N / TY, B * NCHUNK);
    mind_kernel<<<grid, block>>>(img, out);
}